// round 15
// baseline (speedup 1.0000x reference)
#include <cuda_runtime.h>
#include <cuda_fp16.h>
#include <cstdint>

#define BSZ 512
#define HD 512
#define NSTEP 256
#define NUT 32
#define NBLK 128
#define GRPC 32          // CTAs per independent bt-group
#define BM 128
#define NTH 512
// smem ring: K=128 chunks; pitch 272B per 128-half row; A 128 rows, B 64 rows
#define PITCH 272
#define ASLOT (128*PITCH)          // 34816
#define OFF_B ASLOT
#define BUFB (ASLOT + 64*PITCH)    // 52224
#define NBUF 4
#define SMEM_DYN (NBUF*BUFB)       // 208896

// ---------------- persistent device state ----------------
__device__ __align__(16) __half gH0[2][BSZ][HD];
__device__ __align__(16) __half gH1[2][BSZ][HD];
__device__ __align__(16) float gC0[BSZ][HD];
__device__ __align__(16) float gC1[BSZ][HD];
__device__ float gXpart[NUT][BSZ];
__device__ unsigned gBarG[4];
// weights: 12 K128-chunks x 32 u-tiles x (64 gate-rows x 128 k) fp16
__device__ __align__(16) __half gWT[12][NUT][64*128];

// ---------------- helpers ----------------
__device__ __forceinline__ float sigf(float z)     { return 1.0f / (1.0f + __expf(-z)); }
__device__ __forceinline__ float tanhfast(float z) { return 2.0f / (1.0f + __expf(-2.0f * z)) - 1.0f; }

__device__ __forceinline__ uint32_t smem_u32(const void* p) {
    uint32_t a;
    asm("{ .reg .u64 t; cvta.to.shared.u64 t, %1; cvt.u32.u64 %0, t; }" : "=r"(a) : "l"(p));
    return a;
}
__device__ __forceinline__ void cpa16(uint32_t d, const void* s) {
    asm volatile("cp.async.cg.shared.global [%0], [%1], 16;"
                 :: "r"(d), "l"(__cvta_generic_to_global(s)) : "memory");
}
#define CP_COMMIT() asm volatile("cp.async.commit_group;" ::: "memory")
#define CP_WAIT2()  asm volatile("cp.async.wait_group 2;" ::: "memory")
#define CP_WAIT1()  asm volatile("cp.async.wait_group 1;" ::: "memory")
#define CP_WAIT0()  asm volatile("cp.async.wait_group 0;" ::: "memory")

#define LDX4(r, a) \
    asm volatile("ldmatrix.sync.aligned.m8n8.x4.shared.b16 {%0,%1,%2,%3}, [%4];" \
        : "=r"((r)[0]), "=r"((r)[1]), "=r"((r)[2]), "=r"((r)[3]) : "r"(a))

#define MMA(d, a, b) \
    asm volatile("mma.sync.aligned.m16n8k16.row.col.f32.f16.f16.f32 " \
        "{%0,%1,%2,%3}, {%4,%5,%6,%7}, {%8,%9}, {%0,%1,%2,%3};" \
        : "+f"((d)[0]), "+f"((d)[1]), "+f"((d)[2]), "+f"((d)[3]) \
        : "r"((a)[0]), "r"((a)[1]), "r"((a)[2]), "r"((a)[3]), "r"((b)[0]), "r"((b)[1]))

// ---------------- init: states + fp16 weight transform ----------------
__global__ void init_kernel(const float* __restrict__ h, const float* __restrict__ c,
                            const float* __restrict__ W_hh0, const float* __restrict__ W_ih1,
                            const float* __restrict__ W_hh1)
{
    const int gtid = blockIdx.x * blockDim.x + threadIdx.x;
    const int gsz  = gridDim.x * blockDim.x;
    if (gtid < 4) gBarG[gtid] = 0u;

    const int n = BSZ * HD;
    for (int i = gtid; i < n; i += gsz) {
        (&gH0[0][0][0])[i] = __float2half(h[i]);
        (&gH1[0][0][0])[i] = __float2half(h[n + i]);
        (&gC0[0][0])[i] = c[i];
        (&gC1[0][0])[i] = c[n + i];
    }

    const long WN = 12L * NUT * 64 * 128;
    for (long idx = gtid; idx < WN; idx += gsz) {
        const int kk   = (int)(idx & 127);
        const int nrow = (int)((idx >> 7) & 63);
        const int ut   = (int)((idx >> 13) & 31);
        const int ch   = (int)(idx >> 18);
        const float* W = (ch < 4) ? W_hh0 : ((ch < 8) ? W_ih1 : W_hh1);
        // gate-row r -> weight row j: gate = r&3, unit = r>>2
        const int j = (nrow & 3) * HD + ut * 16 + (nrow >> 2);
        gWT[ch][ut][nrow * 128 + kk] = __float2half(W[(size_t)j * HD + (ch & 3) * 128 + kk]);
    }
}

// ---------------- main persistent kernel ----------------
__global__ void __launch_bounds__(NTH, 1) lstm_tc_kernel(
    const float* __restrict__ W_ih0,
    const float* __restrict__ b_ih0, const float* __restrict__ b_hh0,
    const float* __restrict__ b_ih1, const float* __restrict__ b_hh1,
    const float* __restrict__ fc_w,  const float* __restrict__ fc_b,
    float* __restrict__ out)
{
    extern __shared__ unsigned char sbuf[];

    __shared__ float sx[BM];
    __shared__ float sp[4][BM];
    __shared__ float sbias0[64], swih0[64], sbias1[64], sfcw16[16];

    const int tid = threadIdx.x;
    const int lid = tid & 31;
    const int wid = tid >> 5;
    const int wm  = wid & 3;          // M tile: rows wm*32..+31
    const int wn  = wid >> 2;         // N tile: gate-rows wn*16..+15 (units wn*4..+3)
    const int bt  = blockIdx.x >> 5;
    const int ut  = blockIdx.x & 31;
    const int b0  = bt * BM;
    const int u0  = ut * 16;
    const float fcb = fc_b[0];
    const uint32_t sb32 = smem_u32(sbuf);

    if (tid < 64) {
        const int lu = tid >> 2, g = tid & 3;
        const int j = g * HD + u0 + lu;
        sbias0[tid] = b_ih0[j] + b_hh0[j];
        swih0[tid]  = W_ih0[j];
        sbias1[tid] = b_ih1[j] + b_hh1[j];
    }
    if (tid < 16) sfcw16[tid] = fc_w[u0 + tid];
    __syncthreads();

    float acc[2][2][4];

    auto bar_arrive = [&]() {
        __threadfence();
        __syncthreads();
        if (tid == 0) atomicAdd(&gBarG[bt], 1u);
    };
    auto bar_wait = [&](unsigned narr) {
        if (tid == 0) {
            const unsigned target = narr * GRPC;
            while (*((volatile unsigned*)&gBarG[bt]) < target) __nanosleep(32);
        }
        __syncthreads();
    };

    // ---- chunk map: 0..3 = gH0[rp]; 4..7 = gH0[wp]; 8..11 = gH1[rp]; K=128 each
    auto stageA = [&](int c, int r, int rp, int wp) {
        const __half* Ah; int k0;
        if (c < 4)      { Ah = &gH0[rp][0][0]; k0 = c * 128; }
        else if (c < 8) { Ah = &gH0[wp][0][0]; k0 = (c - 4) * 128; }
        else            { Ah = &gH1[rp][0][0]; k0 = (c - 8) * 128; }
        const uint32_t bb = sb32 + r * BUFB;
        #pragma unroll
        for (int i = 0; i < 4; ++i) {   // A: 2048 segs (128 rows x 16)
            const int s = tid + i * NTH;
            const int row = s >> 4, seg = s & 15;
            cpa16(bb + row * PITCH + seg * 16,
                  Ah + (size_t)(b0 + row) * HD + k0 + seg * 8);
        }
        #pragma unroll
        for (int i = 0; i < 2; ++i) {   // B: 1024 segs (64 rows x 16)
            const int s = tid + i * NTH;
            const int row = s >> 4, seg = s & 15;
            cpa16(bb + OFF_B + row * PITCH + seg * 16,
                  &gWT[c][ut][row * 128 + seg * 8]);
        }
        CP_COMMIT();
    };

    // ---- compute one K=128 chunk from ring slot r into acc
    auto compute = [&](int r) {
        const uint32_t bb = sb32 + r * BUFB;
        const uint32_t aoff = (wm * 32 + (lid & 15)) * PITCH + (lid >> 4) * 16;
        const uint32_t boff = OFF_B + (wn * 16 + (lid & 15)) * PITCH + (lid >> 4) * 16;
        #pragma unroll
        for (int ks = 0; ks < 8; ++ks) {
            const uint32_t ko = ks * 32;
            uint32_t Af[2][4];
            LDX4(Af[0], bb + aoff + ko);
            LDX4(Af[1], bb + aoff + 16 * PITCH + ko);
            uint32_t t0[4];
            LDX4(t0, bb + boff + ko);
            uint32_t Bf[2][2];
            Bf[0][0] = t0[0]; Bf[0][1] = t0[2];
            Bf[1][0] = t0[1]; Bf[1][1] = t0[3];
            #pragma unroll
            for (int mt = 0; mt < 2; ++mt)
                #pragma unroll
                for (int nt = 0; nt < 2; ++nt)
                    MMA(acc[mt][nt], Af[mt], Bf[nt]);
        }
    };

    auto zacc = [&]() {
        #pragma unroll
        for (int mt = 0; mt < 2; ++mt)
            #pragma unroll
            for (int nt = 0; nt < 2; ++nt)
                #pragma unroll
                for (int q = 0; q < 4; ++q) acc[mt][nt][q] = 0.0f;
    };

    // ---- fused LSTM epilogue from register accumulators
    const int mbase = wm * 32 + (lid >> 2) + ((lid & 1) ? 8 : 0);
    const int lusub = wn * 4 + ((lid & 3) >> 1);

    auto epilogue = [&](bool L1ph, const float* sbias, float* Cbase, __half* Hb) {
        #pragma unroll
        for (int mt = 0; mt < 2; ++mt) {
            const int bl = mbase + mt * 16;
            const float xb = L1ph ? 0.0f : sx[bl];
            float pb = 0.0f;
            #pragma unroll
            for (int nt = 0; nt < 2; ++nt) {
                float* d = acc[mt][nt];
                const float e0 = __shfl_xor_sync(0xFFFFFFFFu, d[0], 1);
                const float e1 = __shfl_xor_sync(0xFFFFFFFFu, d[1], 1);
                const float e2 = __shfl_xor_sync(0xFFFFFFFFu, d[2], 1);
                const float e3 = __shfl_xor_sync(0xFFFFFFFFu, d[3], 1);
                float gi, gf, gg, go;
                if (!(lid & 1)) { gi = d[0]; gf = d[1]; gg = e0; go = e1; }
                else            { gi = e2;  gf = e3;  gg = d[2]; go = d[3]; }
                const int lun = lusub + nt * 2;
                gi += sbias[4*lun+0]; gf += sbias[4*lun+1];
                gg += sbias[4*lun+2]; go += sbias[4*lun+3];
                if (!L1ph) {
                    gi += xb * swih0[4*lun+0]; gf += xb * swih0[4*lun+1];
                    gg += xb * swih0[4*lun+2]; go += xb * swih0[4*lun+3];
                }
                const size_t off = (size_t)(b0 + bl) * HD + u0 + lun;
                const float cold = Cbase[off];
                const float cn = sigf(gf) * cold + sigf(gi) * tanhfast(gg);
                const float hn = sigf(go) * tanhfast(cn);
                Cbase[off] = cn;
                Hb[off] = __float2half(hn);
                if (L1ph) pb += hn * sfcw16[lun];
            }
            if (L1ph) {
                pb += __shfl_xor_sync(0xFFFFFFFFu, pb, 2);
                if (!(lid & 2)) sp[wn][bl] = pb;
            }
        }
    };

    // ---- prime: stage chunks 0,1 of step 0 (rp=0, wp=1)
    int ss = 0, cs = 0;
    auto nx = [](int v) { return (v + 1) & (NBUF - 1); };
    stageA(0, ss, 0, 1); ss = nx(ss);
    stageA(1, ss, 0, 1); ss = nx(ss);

    #pragma unroll 1
    for (int t = 0; t < NSTEP; ++t) {
        const int rp = t & 1, wp = rp ^ 1;
        const bool last = (t + 1 == NSTEP);

        // ---- layer-0 GEMM chunks 0..3 (guarded by mid barrier of t-1)
        zacc();
        #pragma unroll 1
        for (int i = 0; i < 4; ++i) {
            if (i + 2 < 4)   { stageA(i + 2, ss, rp, wp); ss = nx(ss); CP_WAIT2(); }
            else if (i == 2) CP_WAIT1();
            else             CP_WAIT0();
            __syncthreads();
            compute(cs); cs = nx(cs);
        }

        // ---- end barrier of t-1: wait here (hidden behind L0 chunks)
        if (t > 0) bar_wait(2u * (unsigned)t);

        // ---- gH1[rp], gXpart stable: stage L1 h1-heads, compute sx
        stageA(8, ss, rp, wp); ss = nx(ss);
        stageA(9, ss, rp, wp); ss = nx(ss);
        if (t == 0) {
            if (tid < BM) sx[tid] = 0.0f;
        } else if (tid < BM) {
            float x = fcb;
            #pragma unroll
            for (int j = 0; j < NUT; ++j) x += __ldcg(&gXpart[j][b0 + tid]);
            sx[tid] = x;
            if (ut == 0) out[(size_t)(b0 + tid) * NSTEP + (t - 1)] = x;
        }
        __syncthreads();

        // ---- layer-0 epilogue, mid arrive
        epilogue(false, sbias0, &gC0[0][0], &gH0[wp][0][0]);
        bar_arrive();                       // arrivals: 2t+1

        // ---- layer-1 h1-part: chunks 8..11 (end barrier already satisfied)
        zacc();
        #pragma unroll 1
        for (int i = 0; i < 4; ++i) {
            if (i + 2 < 4)   { stageA(8 + i + 2, ss, rp, wp); ss = nx(ss); CP_WAIT2(); }
            else if (i == 2) CP_WAIT1();
            else             CP_WAIT0();
            __syncthreads();
            compute(cs); cs = nx(cs);
        }

        // ---- mid barrier wait (hidden behind h1-chunks)
        bar_wait(2u * (unsigned)t + 1u);

        // ---- layer-1 h0-part: chunks 4..7; tail stages next-step 0,1
        stageA(4, ss, rp, wp); ss = nx(ss);
        stageA(5, ss, rp, wp); ss = nx(ss);
        #pragma unroll 1
        for (int i = 0; i < 4; ++i) {
            if (i + 2 < 4)   { stageA(4 + i + 2, ss, rp, wp); ss = nx(ss); CP_WAIT2(); }
            else if (!last)  { stageA(i + 2 - 4, ss, wp, rp); ss = nx(ss); CP_WAIT2(); }  // next L0: gH0[wp], mid-guarded
            else if (i == 2) CP_WAIT1();
            else             CP_WAIT0();
            __syncthreads();
            compute(cs); cs = nx(cs);
        }

        // ---- layer-1 epilogue + fc partials, end arrive
        epilogue(true, sbias1, &gC1[0][0], &gH1[wp][0][0]);
        __syncthreads();
        if (tid < BM) gXpart[ut][b0 + tid] = sp[0][tid] + sp[1][tid] + sp[2][tid] + sp[3][tid];
        bar_arrive();                       // arrivals: 2t+2
    }

    // ---- final prediction column 255 (needs end barrier of t=255)
    bar_wait(2u * NSTEP);
    if (ut == 0 && tid < BM) {
        float x = fcb;
        #pragma unroll
        for (int j = 0; j < NUT; ++j) x += __ldcg(&gXpart[j][b0 + tid]);
        out[(size_t)(b0 + tid) * NSTEP + 255] = x;
    }
}

extern "C" void kernel_launch(void* const* d_in, const int* in_sizes, int n_in,
                              void* d_out, int out_size)
{
    const float* h     = (const float*)d_in[0];
    const float* c     = (const float*)d_in[1];
    const float* W_ih0 = (const float*)d_in[2];
    const float* W_hh0 = (const float*)d_in[3];
    const float* b_ih0 = (const float*)d_in[4];
    const float* b_hh0 = (const float*)d_in[5];
    const float* W_ih1 = (const float*)d_in[6];
    const float* W_hh1 = (const float*)d_in[7];
    const float* b_ih1 = (const float*)d_in[8];
    const float* b_hh1 = (const float*)d_in[9];
    const float* fc_w  = (const float*)d_in[10];
    const float* fc_b  = (const float*)d_in[11];

    cudaFuncSetAttribute(lstm_tc_kernel, cudaFuncAttributeMaxDynamicSharedMemorySize, SMEM_DYN);

    init_kernel<<<1024, 256>>>(h, c, W_hh0, W_ih1, W_hh1);
    lstm_tc_kernel<<<NBLK, NTH, SMEM_DYN>>>(W_ih0, b_ih0, b_hh0, b_ih1, b_hh1,
                                            fc_w, fc_b, (float*)d_out);
}

// round 16
// speedup vs baseline: 1.4401x; 1.4401x over previous
#include <cuda_runtime.h>
#include <cuda_fp16.h>
#include <cstdint>

#define BSZ 512
#define HD 512
#define NSTEP 256
#define NUT 32
#define NBLK 128
#define GRPC 32          // CTAs per independent bt-group
#define BM 128
#define NTH 256
// smem ring: pitch 144B per 64-half row; A 128 rows, B 64 rows
#define OFF_B  18432
#define BUFB   27648
#define NBUF   4
#define SMEM_DYN (NBUF*BUFB)

// ---------------- persistent device state ----------------
__device__ __align__(16) __half gH0[2][BSZ][HD];
__device__ __align__(16) __half gH1[2][BSZ][HD];
__device__ __align__(16) float gC0[BSZ][HD];
__device__ __align__(16) float gC1[BSZ][HD];
__device__ float gXpart[NUT][BSZ];
__device__ unsigned gBarG[4];
// weights: 24 chunks x 32 u-tiles x (64 gate-rows x 64 k) fp16, k-contiguous
__device__ __align__(16) __half gWT[24][NUT][64*64];

// ---------------- helpers ----------------
__device__ __forceinline__ float sigf(float z)     { return 1.0f / (1.0f + __expf(-z)); }
__device__ __forceinline__ float tanhfast(float z) { return 2.0f / (1.0f + __expf(-2.0f * z)) - 1.0f; }

__device__ __forceinline__ uint32_t smem_u32(const void* p) {
    uint32_t a;
    asm("{ .reg .u64 t; cvta.to.shared.u64 t, %1; cvt.u32.u64 %0, t; }" : "=r"(a) : "l"(p));
    return a;
}
__device__ __forceinline__ void cpa16(uint32_t d, const void* s) {
    asm volatile("cp.async.cg.shared.global [%0], [%1], 16;"
                 :: "r"(d), "l"(__cvta_generic_to_global(s)) : "memory");
}
#define CP_COMMIT() asm volatile("cp.async.commit_group;" ::: "memory")
#define CP_WAIT2()  asm volatile("cp.async.wait_group 2;" ::: "memory")
#define CP_WAIT1()  asm volatile("cp.async.wait_group 1;" ::: "memory")
#define CP_WAIT0()  asm volatile("cp.async.wait_group 0;" ::: "memory")

#define LDX4(r, a) \
    asm volatile("ldmatrix.sync.aligned.m8n8.x4.shared.b16 {%0,%1,%2,%3}, [%4];" \
        : "=r"((r)[0]), "=r"((r)[1]), "=r"((r)[2]), "=r"((r)[3]) : "r"(a))

#define MMA(d, a, b) \
    asm volatile("mma.sync.aligned.m16n8k16.row.col.f32.f16.f16.f32 " \
        "{%0,%1,%2,%3}, {%4,%5,%6,%7}, {%8,%9}, {%0,%1,%2,%3};" \
        : "+f"((d)[0]), "+f"((d)[1]), "+f"((d)[2]), "+f"((d)[3]) \
        : "r"((a)[0]), "r"((a)[1]), "r"((a)[2]), "r"((a)[3]), "r"((b)[0]), "r"((b)[1]))

// ---------------- init: states + fp16 weight transform ----------------
__global__ void init_kernel(const float* __restrict__ h, const float* __restrict__ c,
                            const float* __restrict__ W_hh0, const float* __restrict__ W_ih1,
                            const float* __restrict__ W_hh1)
{
    const int gtid = blockIdx.x * blockDim.x + threadIdx.x;
    const int gsz  = gridDim.x * blockDim.x;
    if (gtid < 4) gBarG[gtid] = 0u;

    const int n = BSZ * HD;
    for (int i = gtid; i < n; i += gsz) {
        (&gH0[0][0][0])[i] = __float2half(h[i]);
        (&gH1[0][0][0])[i] = __float2half(h[n + i]);
        (&gC0[0][0])[i] = c[i];
        (&gC1[0][0])[i] = c[n + i];
    }

    const long WN = 24L * NUT * 64 * 64;
    for (long idx = gtid; idx < WN; idx += gsz) {
        const int kk   = (int)(idx & 63);
        const int nrow = (int)((idx >> 6) & 63);
        const int ut   = (int)((idx >> 12) & 31);
        const int ch   = (int)(idx >> 17);
        const float* W = (ch < 8) ? W_hh0 : ((ch < 16) ? W_ih1 : W_hh1);
        // gate-row r -> weight row j: gate = r&3, unit = r>>2
        const int j = (nrow & 3) * HD + ut * 16 + (nrow >> 2);
        gWT[ch][ut][nrow * 64 + kk] = __float2half(W[(size_t)j * HD + (ch & 7) * 64 + kk]);
    }
}

// ---------------- main persistent kernel ----------------
__global__ void __launch_bounds__(NTH, 1) lstm_tc_kernel(
    const float* __restrict__ W_ih0,
    const float* __restrict__ b_ih0, const float* __restrict__ b_hh0,
    const float* __restrict__ b_ih1, const float* __restrict__ b_hh1,
    const float* __restrict__ fc_w,  const float* __restrict__ fc_b,
    float* __restrict__ out)
{
    extern __shared__ unsigned char sbuf[];

    __shared__ float sx[BM];
    __shared__ float sp[2][BM];
    __shared__ float sbias0[64], swih0[64], sbias1[64], sfcw16[16];

    const int tid = threadIdx.x;
    const int lid = tid & 31;
    const int wid = tid >> 5;
    const int wm  = wid & 3;          // M tile: rows wm*32..+31 (4 groups)
    const int wn  = wid >> 2;         // N tile: gate-rows wn*32..+31 (2 groups)
    const int bt  = blockIdx.x >> 5;
    const int ut  = blockIdx.x & 31;
    const int b0  = bt * BM;
    const int u0  = ut * 16;
    const float fcb = fc_b[0];
    const uint32_t sb32 = smem_u32(sbuf);

    if (tid < 64) {
        const int lu = tid >> 2, g = tid & 3;
        const int j = g * HD + u0 + lu;
        sbias0[tid] = b_ih0[j] + b_hh0[j];
        swih0[tid]  = W_ih0[j];
        sbias1[tid] = b_ih1[j] + b_hh1[j];
    }
    if (tid < 16) sfcw16[tid] = fc_w[u0 + tid];
    __syncthreads();

    float acc[2][4][4];

    auto bar_arrive = [&]() {
        __threadfence();
        __syncthreads();
        if (tid == 0) atomicAdd(&gBarG[bt], 1u);
    };
    auto bar_wait = [&](unsigned narr) {
        if (tid == 0) {
            const unsigned target = narr * GRPC;
            while (*((volatile unsigned*)&gBarG[bt]) < target) __nanosleep(32);
        }
        __syncthreads();
    };

    // ---- stage chunk c into ring slot r with given read/write phases
    auto stageA = [&](int c, int r, int rp, int wp) {
        const __half* Ah; int k0;
        if (c < 8)       { Ah = &gH0[rp][0][0]; k0 = c * 64; }
        else if (c < 16) { Ah = &gH0[wp][0][0]; k0 = (c - 8) * 64; }
        else             { Ah = &gH1[rp][0][0]; k0 = (c - 16) * 64; }
        const uint32_t bb = sb32 + r * BUFB;
        #pragma unroll
        for (int i = 0; i < 4; ++i) {   // A: 1024 segs (128 rows x 8)
            const int s = tid + i * NTH;
            const int row = s >> 3, seg = s & 7;
            cpa16(bb + row * 144 + seg * 16,
                  Ah + (size_t)(b0 + row) * HD + k0 + seg * 8);
        }
        #pragma unroll
        for (int i = 0; i < 2; ++i) {   // B: 512 segs (64 rows x 8)
            const int s = tid + i * NTH;
            const int row = s >> 3, seg = s & 7;
            cpa16(bb + OFF_B + row * 144 + seg * 16,
                  &gWT[c][ut][row * 64 + seg * 8]);
        }
        CP_COMMIT();
    };

    // ---- compute one K=64 chunk from ring slot r into acc (M32 x N32 per warp)
    auto compute = [&](int r) {
        const uint32_t bb = sb32 + r * BUFB;
        const uint32_t aoff = (wm * 32 + (lid & 15)) * 144 + (lid >> 4) * 16;
        const uint32_t boff = OFF_B + (wn * 32 + (lid & 15)) * 144 + (lid >> 4) * 16;
        #pragma unroll
        for (int ks = 0; ks < 4; ++ks) {
            const uint32_t ko = ks * 32;
            uint32_t Af[2][4];
            LDX4(Af[0], bb + aoff + ko);
            LDX4(Af[1], bb + aoff + 16 * 144 + ko);
            uint32_t t0[4], t1[4];
            LDX4(t0, bb + boff + ko);
            LDX4(t1, bb + boff + 16 * 144 + ko);
            uint32_t Bf[4][2];
            Bf[0][0] = t0[0]; Bf[0][1] = t0[2];
            Bf[1][0] = t0[1]; Bf[1][1] = t0[3];
            Bf[2][0] = t1[0]; Bf[2][1] = t1[2];
            Bf[3][0] = t1[1]; Bf[3][1] = t1[3];
            #pragma unroll
            for (int mt = 0; mt < 2; ++mt)
                #pragma unroll
                for (int nt = 0; nt < 4; ++nt)
                    MMA(acc[mt][nt], Af[mt], Bf[nt]);
        }
    };

    auto zacc = [&]() {
        #pragma unroll
        for (int mt = 0; mt < 2; ++mt)
            #pragma unroll
            for (int nt = 0; nt < 4; ++nt)
                #pragma unroll
                for (int q = 0; q < 4; ++q) acc[mt][nt][q] = 0.0f;
    };

    // ---- fused LSTM epilogue from register accumulators
    const int mbase = wm * 32 + (lid >> 2) + ((lid & 1) ? 8 : 0);
    const int lusub = wn * 8 + ((lid & 3) >> 1);

    auto epilogue = [&](bool L1ph, const float* sbias, float* Cbase, __half* Hb) {
        #pragma unroll
        for (int mt = 0; mt < 2; ++mt) {
            const int bl = mbase + mt * 16;
            const float xb = L1ph ? 0.0f : sx[bl];
            float pb = 0.0f;
            #pragma unroll
            for (int nt = 0; nt < 4; ++nt) {
                float* d = acc[mt][nt];
                const float e0 = __shfl_xor_sync(0xFFFFFFFFu, d[0], 1);
                const float e1 = __shfl_xor_sync(0xFFFFFFFFu, d[1], 1);
                const float e2 = __shfl_xor_sync(0xFFFFFFFFu, d[2], 1);
                const float e3 = __shfl_xor_sync(0xFFFFFFFFu, d[3], 1);
                float gi, gf, gg, go;
                if (!(lid & 1)) { gi = d[0]; gf = d[1]; gg = e0; go = e1; }
                else            { gi = e2;  gf = e3;  gg = d[2]; go = d[3]; }
                const int lun = lusub + nt * 2;
                gi += sbias[4*lun+0]; gf += sbias[4*lun+1];
                gg += sbias[4*lun+2]; go += sbias[4*lun+3];
                if (!L1ph) {
                    gi += xb * swih0[4*lun+0]; gf += xb * swih0[4*lun+1];
                    gg += xb * swih0[4*lun+2]; go += xb * swih0[4*lun+3];
                }
                const size_t off = (size_t)(b0 + bl) * HD + u0 + lun;
                const float cold = Cbase[off];
                const float cn = sigf(gf) * cold + sigf(gi) * tanhfast(gg);
                const float hn = sigf(go) * tanhfast(cn);
                Cbase[off] = cn;
                Hb[off] = __float2half(hn);
                if (L1ph) pb += hn * sfcw16[lun];
            }
            if (L1ph) {
                pb += __shfl_xor_sync(0xFFFFFFFFu, pb, 2);
                if (!(lid & 2)) sp[wn][bl] = pb;
            }
        }
    };

    // ---- prime: stage chunks 0,1 of step 0 (rp=0, wp=1)
    int ss = 0, cs = 0;
    auto nx = [](int v) { return (v + 1) & (NBUF - 1); };
    stageA(0, ss, 0, 1); ss = nx(ss);
    stageA(1, ss, 0, 1); ss = nx(ss);

    #pragma unroll 1
    for (int t = 0; t < NSTEP; ++t) {
        const int rp = t & 1, wp = rp ^ 1;
        const bool last = (t + 1 == NSTEP);

        // ---- layer-0 GEMM chunks 0..7 (guarded by mid barrier of t-1)
        zacc();
        #pragma unroll 1
        for (int i = 0; i < 8; ++i) {
            if (i + 2 < 8) { stageA(i + 2, ss, rp, wp); ss = nx(ss); CP_WAIT2(); }
            else if (i == 6) CP_WAIT1();
            else if (i == 7) CP_WAIT0();
            __syncthreads();
            compute(cs); cs = nx(cs);
        }

        // ---- end barrier of t-1: wait here (hidden behind the 8 chunks above)
        if (t > 0) bar_wait(2u * (unsigned)t);

        // ---- gH1[rp], gXpart stable: stage L1 heads, compute sx
        stageA(16, ss, rp, wp); ss = nx(ss);
        stageA(17, ss, rp, wp); ss = nx(ss);
        if (t == 0) {
            if (tid < BM) sx[tid] = 0.0f;
        } else if (tid < BM) {
            float x = fcb;
            #pragma unroll
            for (int j = 0; j < NUT; ++j) x += __ldcg(&gXpart[j][b0 + tid]);
            sx[tid] = x;
            if (ut == 0) out[(size_t)(b0 + tid) * NSTEP + (t - 1)] = x;
        }
        __syncthreads();

        // ---- layer-0 epilogue, then mid arrive
        epilogue(false, sbias0, &gC0[0][0], &gH0[wp][0][0]);
        bar_arrive();                       // arrivals: 2t+1

        // ---- layer-1 h1-part: chunks 16..23 (needs only end barrier, done)
        zacc();
        #pragma unroll 1
        for (int i = 0; i < 8; ++i) {
            if (i + 2 < 8) { stageA(16 + i + 2, ss, rp, wp); ss = nx(ss); CP_WAIT2(); }
            else if (i == 6) CP_WAIT1();
            else if (i == 7) CP_WAIT0();
            __syncthreads();
            compute(cs); cs = nx(cs);
        }

        // ---- mid barrier wait (hidden behind the 8 h1-chunks)
        bar_wait(2u * (unsigned)t + 1u);

        // ---- layer-1 h0-part: chunks 8..15; tail stages next-step 0,1
        stageA(8, ss, rp, wp); ss = nx(ss);
        stageA(9, ss, rp, wp); ss = nx(ss);
        #pragma unroll 1
        for (int i = 0; i < 8; ++i) {
            if (i + 2 < 8)  { stageA(8 + i + 2, ss, rp, wp); ss = nx(ss); CP_WAIT2(); }
            else if (!last) { stageA(i + 2 - 8, ss, wp, rp); ss = nx(ss); CP_WAIT2(); }  // next L0: gH0[wp], mid-guarded
            else if (i == 6) CP_WAIT1();
            else             CP_WAIT0();
            __syncthreads();
            compute(cs); cs = nx(cs);
        }

        // ---- layer-1 epilogue + fc partials, end arrive
        epilogue(true, sbias1, &gC1[0][0], &gH1[wp][0][0]);
        __syncthreads();
        if (tid < BM) gXpart[ut][b0 + tid] = sp[0][tid] + sp[1][tid];
        bar_arrive();                       // arrivals: 2t+2
    }

    // ---- final prediction column 255 (needs end barrier of t=255)
    bar_wait(2u * NSTEP);
    if (ut == 0 && tid < BM) {
        float x = fcb;
        #pragma unroll
        for (int j = 0; j < NUT; ++j) x += __ldcg(&gXpart[j][b0 + tid]);
        out[(size_t)(b0 + tid) * NSTEP + 255] = x;
    }
}

extern "C" void kernel_launch(void* const* d_in, const int* in_sizes, int n_in,
                              void* d_out, int out_size)
{
    const float* h     = (const float*)d_in[0];
    const float* c     = (const float*)d_in[1];
    const float* W_ih0 = (const float*)d_in[2];
    const float* W_hh0 = (const float*)d_in[3];
    const float* b_ih0 = (const float*)d_in[4];
    const float* b_hh0 = (const float*)d_in[5];
    const float* W_ih1 = (const float*)d_in[6];
    const float* W_hh1 = (const float*)d_in[7];
    const float* b_ih1 = (const float*)d_in[8];
    const float* b_hh1 = (const float*)d_in[9];
    const float* fc_w  = (const float*)d_in[10];
    const float* fc_b  = (const float*)d_in[11];

    cudaFuncSetAttribute(lstm_tc_kernel, cudaFuncAttributeMaxDynamicSharedMemorySize, SMEM_DYN);

    init_kernel<<<1024, 256>>>(h, c, W_hh0, W_ih1, W_hh1);
    lstm_tc_kernel<<<NBLK, NTH, SMEM_DYN>>>(W_ih0, b_ih0, b_hh0, b_ih1, b_hh1,
                                            fc_w, fc_b, (float*)d_out);
}